// round 10
// baseline (speedup 1.0000x reference)
#include <cuda_runtime.h>
#include <cuda_bf16.h>
#include <math.h>
#include <stdint.h>

// Problem constants
#define BB 4096     // batch
#define CC 1000     // classes
#define DD 128      // feature dim
#define QQ 65536    // queue length
#define PROTO_M 0.99f

// ---- output layout (flat float32 concat, reference return order) ----
static const size_t OFF_CLASSFY = 0;
static const size_t OFF_CLUSTER = (size_t)BB * CC;
static const size_t OFF_CONTF   = OFF_CLUSTER + (size_t)BB * CC;
static const size_t OFF_CONTL   = OFF_CONTF + (size_t)(2 * BB + QQ) * DD;
static const size_t OFF_PROTO   = OFF_CONTL + (size_t)(2 * BB + QQ);
static const size_t OFF_QUEUE   = OFF_PROTO + (size_t)CC * DD;
static const size_t OFF_QP      = OFF_QUEUE + (size_t)QQ * DD;
static const size_t OFF_PTR     = OFF_QP + (size_t)QQ;

// scratch (no allocations allowed -> device globals)
__device__ int g_labels[BB];

// ---------------------------------------------------------------------------
__device__ __forceinline__ int load_ptr_val(const void* p)
{
    int iv = *(const int*)p;
    if (iv >= 0 && iv <= QQ) return iv;       // stored as int32
    float fv = *(const float*)p;              // stored as float32
    return (int)fv;
}
__device__ __forceinline__ int clamp_ptr(int ptr)
{
    int ptrc = ptr;
    if (ptrc < 0) ptrc = 0;
    if (ptrc > QQ - BB) ptrc = QQ - BB;
    return ptrc;
}

// ---------------------------------------------------------------------------
// tf32 helpers
// ---------------------------------------------------------------------------
__device__ __forceinline__ uint32_t f32_to_tf32(float f)
{
    uint32_t r;
    asm volatile("cvt.rna.tf32.f32 %0, %1;" : "=r"(r) : "f"(f));
    return r;
}

__device__ __forceinline__ void mma_tf32(float c[4],
    uint32_t a0, uint32_t a1, uint32_t a2, uint32_t a3,
    uint32_t b0, uint32_t b1)
{
    asm volatile(
        "mma.sync.aligned.m16n8k8.row.col.f32.tf32.tf32.f32 "
        "{%0,%1,%2,%3}, {%4,%5,%6,%7}, {%8,%9}, {%0,%1,%2,%3};"
        : "+f"(c[0]), "+f"(c[1]), "+f"(c[2]), "+f"(c[3])
        : "r"(a0), "r"(a1), "r"(a2), "r"(a3), "r"(b0), "r"(b1));
}

// GEMM: block owns 64 rows x full CC cols. A (64x128) resident; B streamed
// in 16 tiles of 64 classes. Fused softmax: exp-store + row sums + in-place
// rescale (re-read hits L2).
#define TBM 64
#define TBNT 64                    // per-iteration N tile
#define NT_ITERS 16                // ceil(1000/64)
#define LDP (DD + 4)               // 132 words per smem row (full K)
#define GEMM_SMEM_BYTES ((TBM + TBNT) * LDP * 4)   // 67,584 bytes

// head interleave: groups of 17 = [1 gemm, 8 classfy, 8 bulk] x 64
#define HEAD_GRID (64 * 17)        // 1088

// ---------------------------------------------------------------------------
// gemm role: cluster_out[m0:m0+64, :] = softmax(q @ protos^T) fully fused.
// ---------------------------------------------------------------------------
__device__ void gemm_role(int gb, uint32_t* smem,
    const float* __restrict__ Aq, const float* __restrict__ Bp,
    float* __restrict__ Cout)
{
    uint32_t* As = smem;                  // [TBM][LDP]
    uint32_t* Bs = smem + TBM * LDP;      // [TBNT][LDP]
    __shared__ float smem_part[TBM][4];
    __shared__ float rowinv[TBM];

    const int tid  = threadIdx.x;
    const int lane = tid & 31;
    const int w    = tid >> 5;
    const int wm   = w & 1;               // 2 m-warps of 32 rows
    const int wn   = w >> 1;              // 4 n-warps of 16 cols
    const int g    = lane >> 2;           // 0..7
    const int tig  = lane & 3;            // 0..3
    const int m0   = gb * TBM;
    const int rbase = wm * 32;
    const int cbase = wn * 16;

    // ---- load A (64 x 128) once, interleaved-pair layout ----
#pragma unroll
    for (int it = 0; it < 4; it++) {
        int slot = it * 256 + tid;        // 0..1023 = 64 rows x 16 groups
        int r = slot >> 4, gp = slot & 15;
        const float* src = Aq + (size_t)(m0 + r) * DD + gp * 8;
        float4 lo = *(const float4*)src;
        float4 hi = *(const float4*)(src + 4);
        uint32_t* dst = As + r * LDP + gp * 8;
        uint4 o0, o1;
        o0.x = f32_to_tf32(lo.x); o0.y = f32_to_tf32(hi.x);
        o0.z = f32_to_tf32(lo.y); o0.w = f32_to_tf32(hi.y);
        o1.x = f32_to_tf32(lo.z); o1.y = f32_to_tf32(hi.z);
        o1.z = f32_to_tf32(lo.w); o1.w = f32_to_tf32(hi.w);
        *(uint4*)dst = o0;
        *(uint4*)(dst + 4) = o1;
    }

    float rs[2][2] = {{0.f, 0.f}, {0.f, 0.f}};   // running row sums [mt][half]

    for (int nt = 0; nt < NT_ITERS; nt++) {
        const int n0 = nt * TBNT;
        if (nt > 0) __syncthreads();      // previous B fully consumed
        // ---- load B tile (64 classes x 128 K) ----
#pragma unroll
        for (int it = 0; it < 4; it++) {
            int slot = it * 256 + tid;    // 64 rows x 16 groups
            int r = slot >> 4, gp = slot & 15;
            int n = n0 + r;
            float4 lo, hi;
            if (n < CC) {
                const float* src = Bp + (size_t)n * DD + gp * 8;
                lo = *(const float4*)src;
                hi = *(const float4*)(src + 4);
            } else {
                lo = make_float4(0.f, 0.f, 0.f, 0.f);
                hi = lo;
            }
            uint32_t* dst = Bs + r * LDP + gp * 8;
            uint4 o0, o1;
            o0.x = f32_to_tf32(lo.x); o0.y = f32_to_tf32(hi.x);
            o0.z = f32_to_tf32(lo.y); o0.w = f32_to_tf32(hi.y);
            o1.x = f32_to_tf32(lo.z); o1.y = f32_to_tf32(hi.z);
            o1.z = f32_to_tf32(lo.w); o1.w = f32_to_tf32(hi.w);
            *(uint4*)dst = o0;
            *(uint4*)(dst + 4) = o1;
        }
        __syncthreads();

        float c[2][2][4];
#pragma unroll
        for (int mt = 0; mt < 2; mt++)
#pragma unroll
            for (int n2 = 0; n2 < 2; n2++)
#pragma unroll
                for (int i = 0; i < 4; i++) c[mt][n2][i] = 0.f;

#pragma unroll
        for (int ks = 0; ks < DD / 8; ks++) {
            const int k0 = ks * 8;
            uint2 afr[2][2];
#pragma unroll
            for (int mt = 0; mt < 2; mt++) {
                int rb = rbase + mt * 16 + g;
                afr[mt][0] = *(const uint2*)(As + rb * LDP + k0 + 2 * tig);
                afr[mt][1] = *(const uint2*)(As + (rb + 8) * LDP + k0 + 2 * tig);
            }
            uint2 bfr[2];
#pragma unroll
            for (int n2 = 0; n2 < 2; n2++) {
                int cb = cbase + n2 * 8 + g;
                bfr[n2] = *(const uint2*)(Bs + cb * LDP + k0 + 2 * tig);
            }
#pragma unroll
            for (int mt = 0; mt < 2; mt++)
#pragma unroll
                for (int n2 = 0; n2 < 2; n2++)
                    mma_tf32(c[mt][n2],
                             afr[mt][0].x, afr[mt][1].x, afr[mt][0].y, afr[mt][1].y,
                             bfr[n2].x, bfr[n2].y);
        }

        // per-tile epilogue: exp, store (unnormalized), accumulate row sums
#pragma unroll
        for (int mt = 0; mt < 2; mt++) {
#pragma unroll
            for (int n2 = 0; n2 < 2; n2++) {
                int m = m0 + rbase + mt * 16 + g;
                int n = n0 + cbase + n2 * 8 + 2 * tig;
                if (n < CC) {
                    float e0 = __expf(c[mt][n2][0]);
                    float e1 = __expf(c[mt][n2][1]);
                    float e2 = __expf(c[mt][n2][2]);
                    float e3 = __expf(c[mt][n2][3]);
                    *(float2*)(Cout + (size_t)m * CC + n) = make_float2(e0, e1);
                    *(float2*)(Cout + (size_t)(m + 8) * CC + n) = make_float2(e2, e3);
                    rs[mt][0] += e0 + e1;
                    rs[mt][1] += e2 + e3;
                }
            }
        }
    }

    // ---- row sums: reduce across tig lanes, combine across n-warps ----
#pragma unroll
    for (int o = 1; o <= 2; o <<= 1) {
#pragma unroll
        for (int mt = 0; mt < 2; mt++) {
            rs[mt][0] += __shfl_xor_sync(0xffffffffu, rs[mt][0], o);
            rs[mt][1] += __shfl_xor_sync(0xffffffffu, rs[mt][1], o);
        }
    }
    if (tig == 0) {
#pragma unroll
        for (int mt = 0; mt < 2; mt++) {
            smem_part[rbase + mt * 16 + g][wn]     = rs[mt][0];
            smem_part[rbase + mt * 16 + 8 + g][wn] = rs[mt][1];
        }
    }
    __syncthreads();
    if (tid < TBM) {
        float s = smem_part[tid][0] + smem_part[tid][1]
                + smem_part[tid][2] + smem_part[tid][3];
        rowinv[tid] = 1.0f / s;
    }
    __syncthreads();

    // ---- in-place rescale (reads are fresh in L2): 8 rows per warp ----
    const int RF4 = CC / 4;   // 250
#pragma unroll
    for (int rr = 0; rr < 8; rr++) {
        int row = rr * 8 + w;
        float inv = rowinv[row];
        float4* rowp = (float4*)(Cout + (size_t)(m0 + row) * CC);
#pragma unroll
        for (int j = 0; j < 8; j++) {
            int c4 = j * 32 + lane;
            if (c4 < RF4) {
                float4 e = rowp[c4];
                e.x *= inv; e.y *= inv; e.z *= inv; e.w *= inv;
                rowp[c4] = e;
            }
        }
    }
}

// ---------------------------------------------------------------------------
// classfy role: warp-per-row softmax + argmax(softmax*plabel) + labels epi.
// ---------------------------------------------------------------------------
__device__ void classfy_role(int cb,
    const float4* __restrict__ logits4, const float4* __restrict__ plabel4,
    const void* __restrict__ ptr_in,
    float4* __restrict__ out4, int* __restrict__ labels,
    float* __restrict__ cont_labels, float* __restrict__ new_qp,
    float* __restrict__ new_ptr_out)
{
    const int tid  = threadIdx.x;
    const int w    = tid >> 5;
    const int lane = tid & 31;
    const int row  = cb * 8 + w;
    const int RF4  = CC / 4;               // 250
    const float4* lrow = logits4 + (size_t)row * RF4;
    const float4* prow = plabel4 + (size_t)row * RF4;
    float4* orow = out4 + (size_t)row * RF4;

    float4 l[8];
    float mx = -1e30f;
#pragma unroll
    for (int j = 0; j < 8; j++) {
        int c4 = j * 32 + lane;
        if (c4 < RF4) {
            l[j] = lrow[c4];
            mx = fmaxf(mx, fmaxf(fmaxf(l[j].x, l[j].y), fmaxf(l[j].z, l[j].w)));
        } else {
            l[j] = make_float4(-1e30f, -1e30f, -1e30f, -1e30f);
        }
    }
#pragma unroll
    for (int o = 16; o; o >>= 1) mx = fmaxf(mx, __shfl_xor_sync(0xffffffffu, mx, o));

    float sum = 0.f;
#pragma unroll
    for (int j = 0; j < 8; j++) {
        l[j].x = __expf(l[j].x - mx);
        l[j].y = __expf(l[j].y - mx);
        l[j].z = __expf(l[j].z - mx);
        l[j].w = __expf(l[j].w - mx);
        sum += l[j].x + l[j].y + l[j].z + l[j].w;
    }
#pragma unroll
    for (int o = 16; o; o >>= 1) sum += __shfl_xor_sync(0xffffffffu, sum, o);
    const float inv = 1.0f / sum;

    float bv = -1.0f;
    int bi = 0x7fffffff;
#pragma unroll
    for (int j = 0; j < 8; j++) {
        int c4 = j * 32 + lane;
        if (c4 < RF4) {
            float4 p = prow[c4];
            float4 o;
            o.x = l[j].x * inv; o.y = l[j].y * inv;
            o.z = l[j].z * inv; o.w = l[j].w * inv;
            orow[c4] = o;
            float v0 = o.x * p.x, v1 = o.y * p.y, v2 = o.z * p.z, v3 = o.w * p.w;
            if (v0 > bv) { bv = v0; bi = 4 * c4; }
            if (v1 > bv) { bv = v1; bi = 4 * c4 + 1; }
            if (v2 > bv) { bv = v2; bi = 4 * c4 + 2; }
            if (v3 > bv) { bv = v3; bi = 4 * c4 + 3; }
        }
    }
#pragma unroll
    for (int o = 16; o; o >>= 1) {
        float ov = __shfl_xor_sync(0xffffffffu, bv, o);
        int   oi = __shfl_xor_sync(0xffffffffu, bi, o);
        if (ov > bv || (ov == bv && oi < bi)) { bv = ov; bi = oi; }
    }
    if (lane == 0) {
        labels[row] = bi;
        const int ptr = load_ptr_val(ptr_in);
        const int ptrc = clamp_ptr(ptr);
        float lab = (float)bi;
        cont_labels[row] = lab;
        cont_labels[BB + row] = lab;
        new_qp[ptrc + row] = lab;
        if (row == 0) new_ptr_out[0] = (float)((ptr + BB) % QQ);
    }
}

// ---------------------------------------------------------------------------
// bulk role: queue dup + k scatter + q/k dup + qp dup.
// ---------------------------------------------------------------------------
#define NQ4     (QQ * DD / 4)      // 2,097,152
#define NB4     (BB * DD / 4)      // 131,072
#define BULK_SEG (NQ4 / 16)        // 131,072

__device__ void bulk_role(int bb,
    const float4* __restrict__ q4, const float4* __restrict__ k4,
    const float4* __restrict__ queue4, const float* __restrict__ qp,
    const void* __restrict__ ptr_in,
    float4* __restrict__ contf4, float4* __restrict__ outq4,
    float* __restrict__ outqp, float* __restrict__ contl)
{
    const int tid = threadIdx.x;
    const int ptrc = clamp_ptr(load_ptr_val(ptr_in));
    const int i = bb * 256 + tid;     // 0..131071 == NB4, exact

#pragma unroll
    for (int b = 0; b < 4; b++) {
        float4 v[4];
#pragma unroll
        for (int h = 0; h < 4; h++)
            v[h] = __ldcs(&queue4[i + (b * 4 + h) * BULK_SEG]);
#pragma unroll
        for (int h = 0; h < 4; h++)
            __stcs(&contf4[2 * NB4 + i + (b * 4 + h) * BULK_SEG], v[h]);
#pragma unroll
        for (int h = 0; h < 4; h++) {
            int idx = i + (b * 4 + h) * BULK_SEG;
            int row = idx >> 5;                        // 32 float4 per row
            float4 o = v[h];
            if (row >= ptrc && row < ptrc + BB)
                o = __ldcs(&k4[(row - ptrc) * 32 + (idx & 31)]);
            __stcs(&outq4[idx], o);                    // new_queue
        }
    }
    {
        float4 vq = __ldcs(&q4[i]);
        float4 vk = __ldcs(&k4[i]);
        __stcs(&contf4[i], vq);
        __stcs(&contf4[NB4 + i], vk);
    }
    if (i < QQ) {
        float v0 = __ldcs(&qp[i]);
        __stcs(&contl[2 * BB + i], v0);            // cont_labels tail
        if (i < ptrc || i >= ptrc + BB)
            __stcs(&outqp[i], v0);                 // new_queue_pseudo
    }
}

// ---------------------------------------------------------------------------
// Kernel 1: head — groups of 17 = [1 gemm, 8 classfy, 8 bulk] x 64
// ---------------------------------------------------------------------------
__global__ __launch_bounds__(256) void head_kernel(
    const float* __restrict__ q, const float* __restrict__ protos,
    float* __restrict__ cluster_out,
    const float4* __restrict__ logits4, const float4* __restrict__ plabel4,
    const void* __restrict__ ptr_in,
    float4* __restrict__ out_classfy4, int* __restrict__ labels,
    float* __restrict__ cont_labels, float* __restrict__ new_qp,
    float* __restrict__ new_ptr_out,
    const float4* __restrict__ k4, const float4* __restrict__ queue4,
    const float* __restrict__ qp,
    float4* __restrict__ contf4, float4* __restrict__ outq4,
    float* __restrict__ outqp)
{
    extern __shared__ uint32_t smem[];
    const int grp = blockIdx.x / 17;
    const int r   = blockIdx.x % 17;
    if (r == 0) {
        gemm_role(grp, smem, q, protos, cluster_out);
    } else if (r <= 8) {
        classfy_role(grp * 8 + (r - 1), logits4, plabel4, ptr_in,
                     out_classfy4, labels, cont_labels, new_qp, new_ptr_out);
    } else {
        bulk_role(grp * 8 + (r - 9), (const float4*)q, k4, queue4, qp, ptr_in,
                  contf4, outq4, outqp, cont_labels);
    }
}

// ---------------------------------------------------------------------------
// Kernel 2: tail — proto EMA only (1000 blocks), warp-shuffle scan.
// ---------------------------------------------------------------------------
__global__ __launch_bounds__(256) void tail_kernel(
    const float* __restrict__ qf, const float* __restrict__ protos,
    const int* __restrict__ labels, float* __restrict__ out_proto)
{
    const int c    = blockIdx.x;
    const int tid  = threadIdx.x;
    const int w    = tid >> 5;
    const int lane = tid & 31;
    __shared__ int idxbuf[BB];
    __shared__ int wsum[8];
    __shared__ float ws[4];

    const int4* lab4 = (const int4*)labels;
    int4 lv[4];
#pragma unroll
    for (int j = 0; j < 4; j++) lv[j] = __ldg(&lab4[tid * 4 + j]);
    int cnt = 0;
#pragma unroll
    for (int j = 0; j < 4; j++)
        cnt += (lv[j].x == c) + (lv[j].y == c) + (lv[j].z == c) + (lv[j].w == c);

    int inc = cnt;
#pragma unroll
    for (int d = 1; d < 32; d <<= 1) {
        int v = __shfl_up_sync(0xffffffffu, inc, d);
        if (lane >= d) inc += v;
    }
    if (lane == 31) wsum[w] = inc;
    __syncthreads();
    int wbase = 0, total = 0;
#pragma unroll
    for (int u = 0; u < 8; u++) {
        int s = wsum[u];
        if (u < w) wbase += s;
        total += s;
    }
    int wofs = wbase + inc - cnt;
    const int base = tid * 16;
#pragma unroll
    for (int j = 0; j < 4; j++) {
        if (lv[j].x == c) idxbuf[wofs++] = base + 4 * j;
        if (lv[j].y == c) idxbuf[wofs++] = base + 4 * j + 1;
        if (lv[j].z == c) idxbuf[wofs++] = base + 4 * j + 2;
        if (lv[j].w == c) idxbuf[wofs++] = base + 4 * j + 3;
    }
    __syncthreads();

    float acc = 0.f;
    if (tid < DD) {
        acc = protos[(size_t)c * DD + tid];
        for (int j = 0; j < total; j++)
            acc = PROTO_M * acc + (1.0f - PROTO_M) * qf[(size_t)idxbuf[j] * DD + tid];
    }
    float s = acc * acc;
#pragma unroll
    for (int o = 16; o; o >>= 1) s += __shfl_xor_sync(0xffffffffu, s, o);
    if (tid < DD && (tid & 31) == 0) ws[tid >> 5] = s;
    __syncthreads();
    if (tid < DD) {
        float tot = ws[0] + ws[1] + ws[2] + ws[3];
        float inv = 1.0f / fmaxf(sqrtf(tot), 1e-12f);
        out_proto[(size_t)c * DD + tid] = acc * inv;
    }
}

// ---------------------------------------------------------------------------
static bool g_init = false;

extern "C" void kernel_launch(void* const* d_in, const int* in_sizes, int n_in,
                              void* d_out, int out_size)
{
    const float* q       = (const float*)d_in[0];
    const float* k       = (const float*)d_in[1];
    const float* logits  = (const float*)d_in[2];
    const float* plabel  = (const float*)d_in[3];
    const float* protos  = (const float*)d_in[4];
    const float* queue   = (const float*)d_in[5];
    const float* queuep  = (const float*)d_in[6];
    const void*  ptr_in  = d_in[7];

    float* out = (float*)d_out;
    float* out_classfy = out + OFF_CLASSFY;
    float* out_cluster = out + OFF_CLUSTER;
    float* out_contf   = out + OFF_CONTF;
    float* out_contl   = out + OFF_CONTL;
    float* out_proto   = out + OFF_PROTO;
    float* out_queue   = out + OFF_QUEUE;
    float* out_qp      = out + OFF_QP;
    float* out_ptr     = out + OFF_PTR;

    int* labels;
    cudaGetSymbolAddress((void**)&labels, g_labels);

    if (!g_init) {
        cudaFuncSetAttribute(head_kernel,
                             cudaFuncAttributeMaxDynamicSharedMemorySize,
                             GEMM_SMEM_BYTES);
        g_init = true;
    }

    cudaStream_t s = 0;

    // 1) head: fused-softmax gemm + classfy + bulk, interleaved [1,8,8] x 64
    head_kernel<<<HEAD_GRID, 256, GEMM_SMEM_BYTES, s>>>(
        q, protos, out_cluster,
        (const float4*)logits, (const float4*)plabel, ptr_in,
        (float4*)out_classfy, labels, out_contl, out_qp, out_ptr,
        (const float4*)k, (const float4*)queue, queuep,
        (float4*)out_contf, (float4*)out_queue, out_qp);

    // 2) tail: prototype EMA only
    tail_kernel<<<CC, 256, 0, s>>>(q, protos, labels, out_proto);
}

// round 11
// speedup vs baseline: 2.1589x; 2.1589x over previous
#include <cuda_runtime.h>
#include <cuda_bf16.h>
#include <math.h>
#include <stdint.h>

// Problem constants
#define BB 4096     // batch
#define CC 1000     // classes
#define DD 128      // feature dim
#define QQ 65536    // queue length
#define PROTO_M 0.99f

// ---- output layout (flat float32 concat, reference return order) ----
static const size_t OFF_CLASSFY = 0;
static const size_t OFF_CLUSTER = (size_t)BB * CC;
static const size_t OFF_CONTF   = OFF_CLUSTER + (size_t)BB * CC;
static const size_t OFF_CONTL   = OFF_CONTF + (size_t)(2 * BB + QQ) * DD;
static const size_t OFF_PROTO   = OFF_CONTL + (size_t)(2 * BB + QQ);
static const size_t OFF_QUEUE   = OFF_PROTO + (size_t)CC * DD;
static const size_t OFF_QP      = OFF_QUEUE + (size_t)QQ * DD;
static const size_t OFF_PTR     = OFF_QP + (size_t)QQ;

// scratch (no allocations allowed -> device globals)
__device__ float g_logits[(size_t)BB * CC];  // exp(logit) after head
__device__ float g_psum[(size_t)BB * 8];     // per-(row, n-block) exp partial sums
__device__ int   g_labels[BB];

// ---------------------------------------------------------------------------
__device__ __forceinline__ int load_ptr_val(const void* p)
{
    int iv = *(const int*)p;
    if (iv >= 0 && iv <= QQ) return iv;       // stored as int32
    float fv = *(const float*)p;              // stored as float32
    return (int)fv;
}
__device__ __forceinline__ int clamp_ptr(int ptr)
{
    int ptrc = ptr;
    if (ptrc < 0) ptrc = 0;
    if (ptrc > QQ - BB) ptrc = QQ - BB;
    return ptrc;
}

// ---------------------------------------------------------------------------
// tf32 helpers
// ---------------------------------------------------------------------------
__device__ __forceinline__ uint32_t f32_to_tf32(float f)
{
    uint32_t r;
    asm volatile("cvt.rna.tf32.f32 %0, %1;" : "=r"(r) : "f"(f));
    return r;
}

__device__ __forceinline__ void mma_tf32(float c[4],
    uint32_t a0, uint32_t a1, uint32_t a2, uint32_t a3,
    uint32_t b0, uint32_t b1)
{
    asm volatile(
        "mma.sync.aligned.m16n8k8.row.col.f32.tf32.tf32.f32 "
        "{%0,%1,%2,%3}, {%4,%5,%6,%7}, {%8,%9}, {%0,%1,%2,%3};"
        : "+f"(c[0]), "+f"(c[1]), "+f"(c[2]), "+f"(c[3])
        : "r"(a0), "r"(a1), "r"(a2), "r"(a3), "r"(b0), "r"(b1));
}

#define TBM 64
#define TBN 128
#define TBK 64
#define LDPK (TBK + 4)   // 68 words per smem row
#define GEMM_SMEM_BYTES ((TBM + TBN) * LDPK * 4)   // 52,224 bytes

// ---------------------------------------------------------------------------
// gemm role: exp(q @ protos^T) + per-(row, n-block) partial sums.
// ---------------------------------------------------------------------------
__device__ void gemm_role(int gb, uint32_t* smem,
    const float* __restrict__ Aq, const float* __restrict__ Bp,
    float* __restrict__ Eout, float* __restrict__ psum)
{
    uint32_t* As = smem;                  // [TBM][LDPK]
    uint32_t* Bs = smem + TBM * LDPK;     // [TBN][LDPK]
    __shared__ float smem_part[TBM][4];

    const int tid  = threadIdx.x;
    const int lane = tid & 31;
    const int w    = tid >> 5;
    const int wm   = w & 1;
    const int wn   = w >> 1;
    const int g    = lane >> 2;
    const int tig  = lane & 3;
    const int bx   = gb & 7;              // 8 n-blocks
    const int by   = gb >> 3;             // 64 m-blocks
    const int m0   = by * TBM;
    const int n0   = bx * TBN;
    const int rbase = wm * 32;
    const int cbase = wn * 32;

    float c[2][4][4];
#pragma unroll
    for (int mt = 0; mt < 2; mt++)
#pragma unroll
        for (int nt = 0; nt < 4; nt++)
#pragma unroll
            for (int i = 0; i < 4; i++) c[mt][nt][i] = 0.f;

#pragma unroll
    for (int kt = 0; kt < 2; kt++) {
        const int kk = kt * TBK;
        if (kt > 0) __syncthreads();
#pragma unroll
        for (int it = 0; it < 6; it++) {
            int slot = it * 256 + tid;
            float4 lo, hi;
            uint32_t* dst;
            if (slot < TBM * 8) {
                int r = slot >> 3, gp = slot & 7;
                const float* src = Aq + (size_t)(m0 + r) * DD + kk + gp * 8;
                lo = *(const float4*)src;
                hi = *(const float4*)(src + 4);
                dst = As + r * LDPK + gp * 8;
            } else {
                int s = slot - TBM * 8;
                int r = s >> 3, gp = s & 7;
                int n = n0 + r;
                if (n < CC) {
                    const float* src = Bp + (size_t)n * DD + kk + gp * 8;
                    lo = *(const float4*)src;
                    hi = *(const float4*)(src + 4);
                } else {
                    lo = make_float4(0.f, 0.f, 0.f, 0.f);
                    hi = lo;
                }
                dst = Bs + r * LDPK + gp * 8;
            }
            uint4 o0, o1;
            o0.x = f32_to_tf32(lo.x); o0.y = f32_to_tf32(hi.x);
            o0.z = f32_to_tf32(lo.y); o0.w = f32_to_tf32(hi.y);
            o1.x = f32_to_tf32(lo.z); o1.y = f32_to_tf32(hi.z);
            o1.z = f32_to_tf32(lo.w); o1.w = f32_to_tf32(hi.w);
            *(uint4*)dst = o0;
            *(uint4*)(dst + 4) = o1;
        }
        __syncthreads();

#pragma unroll
        for (int ks = 0; ks < TBK / 8; ks++) {
            const int k0 = ks * 8;
            uint2 afr[2][2];
#pragma unroll
            for (int mt = 0; mt < 2; mt++) {
                int rb = rbase + mt * 16 + g;
                afr[mt][0] = *(const uint2*)(As + rb * LDPK + k0 + 2 * tig);
                afr[mt][1] = *(const uint2*)(As + (rb + 8) * LDPK + k0 + 2 * tig);
            }
            uint2 bfr[4];
#pragma unroll
            for (int nt = 0; nt < 4; nt++) {
                int cb = cbase + nt * 8 + g;
                bfr[nt] = *(const uint2*)(Bs + cb * LDPK + k0 + 2 * tig);
            }
#pragma unroll
            for (int mt = 0; mt < 2; mt++)
#pragma unroll
                for (int nt = 0; nt < 4; nt++)
                    mma_tf32(c[mt][nt],
                             afr[mt][0].x, afr[mt][1].x, afr[mt][0].y, afr[mt][1].y,
                             bfr[nt].x, bfr[nt].y);
        }
    }

    // epilogue: exp, store, per-row partial sums (deterministic)
    float rs[2][2] = {{0.f, 0.f}, {0.f, 0.f}};
#pragma unroll
    for (int mt = 0; mt < 2; mt++) {
#pragma unroll
        for (int nt = 0; nt < 4; nt++) {
            int m = m0 + rbase + mt * 16 + g;
            int n = n0 + cbase + nt * 8 + 2 * tig;
            if (n < CC) {
                float e0 = __expf(c[mt][nt][0]);
                float e1 = __expf(c[mt][nt][1]);
                float e2 = __expf(c[mt][nt][2]);
                float e3 = __expf(c[mt][nt][3]);
                *(float2*)(Eout + (size_t)m * CC + n) = make_float2(e0, e1);
                *(float2*)(Eout + (size_t)(m + 8) * CC + n) = make_float2(e2, e3);
                rs[mt][0] += e0 + e1;
                rs[mt][1] += e2 + e3;
            }
        }
    }
#pragma unroll
    for (int o = 1; o <= 2; o <<= 1) {
#pragma unroll
        for (int mt = 0; mt < 2; mt++) {
            rs[mt][0] += __shfl_xor_sync(0xffffffffu, rs[mt][0], o);
            rs[mt][1] += __shfl_xor_sync(0xffffffffu, rs[mt][1], o);
        }
    }
    if (tig == 0) {
#pragma unroll
        for (int mt = 0; mt < 2; mt++) {
            smem_part[rbase + mt * 16 + g][wn]     = rs[mt][0];
            smem_part[rbase + mt * 16 + 8 + g][wn] = rs[mt][1];
        }
    }
    __syncthreads();
    if (tid < TBM) {
        float s = smem_part[tid][0] + smem_part[tid][1]
                + smem_part[tid][2] + smem_part[tid][3];
        psum[(size_t)(m0 + tid) * 8 + bx] = s;
    }
}

// ---------------------------------------------------------------------------
// classfy role: warp-per-row softmax + argmax(softmax*plabel) + labels epi.
// ---------------------------------------------------------------------------
__device__ void classfy_role(int cb,
    const float4* __restrict__ logits4, const float4* __restrict__ plabel4,
    const void* __restrict__ ptr_in,
    float4* __restrict__ out4, int* __restrict__ labels,
    float* __restrict__ cont_labels, float* __restrict__ new_qp,
    float* __restrict__ new_ptr_out)
{
    const int tid  = threadIdx.x;
    const int w    = tid >> 5;
    const int lane = tid & 31;
    const int row  = cb * 8 + w;
    const int RF4  = CC / 4;               // 250
    const float4* lrow = logits4 + (size_t)row * RF4;
    const float4* prow = plabel4 + (size_t)row * RF4;
    float4* orow = out4 + (size_t)row * RF4;

    float4 l[8];
    float mx = -1e30f;
#pragma unroll
    for (int j = 0; j < 8; j++) {
        int c4 = j * 32 + lane;
        if (c4 < RF4) {
            l[j] = __ldcs(&lrow[c4]);
            mx = fmaxf(mx, fmaxf(fmaxf(l[j].x, l[j].y), fmaxf(l[j].z, l[j].w)));
        } else {
            l[j] = make_float4(-1e30f, -1e30f, -1e30f, -1e30f);
        }
    }
#pragma unroll
    for (int o = 16; o; o >>= 1) mx = fmaxf(mx, __shfl_xor_sync(0xffffffffu, mx, o));

    float sum = 0.f;
#pragma unroll
    for (int j = 0; j < 8; j++) {
        l[j].x = __expf(l[j].x - mx);
        l[j].y = __expf(l[j].y - mx);
        l[j].z = __expf(l[j].z - mx);
        l[j].w = __expf(l[j].w - mx);
        sum += l[j].x + l[j].y + l[j].z + l[j].w;
    }
#pragma unroll
    for (int o = 16; o; o >>= 1) sum += __shfl_xor_sync(0xffffffffu, sum, o);
    const float inv = 1.0f / sum;

    float bv = -1.0f;
    int bi = 0x7fffffff;
#pragma unroll
    for (int j = 0; j < 8; j++) {
        int c4 = j * 32 + lane;
        if (c4 < RF4) {
            float4 p = __ldcs(&prow[c4]);
            float4 o;
            o.x = l[j].x * inv; o.y = l[j].y * inv;
            o.z = l[j].z * inv; o.w = l[j].w * inv;
            __stcs(&orow[c4], o);
            float v0 = o.x * p.x, v1 = o.y * p.y, v2 = o.z * p.z, v3 = o.w * p.w;
            if (v0 > bv) { bv = v0; bi = 4 * c4; }
            if (v1 > bv) { bv = v1; bi = 4 * c4 + 1; }
            if (v2 > bv) { bv = v2; bi = 4 * c4 + 2; }
            if (v3 > bv) { bv = v3; bi = 4 * c4 + 3; }
        }
    }
#pragma unroll
    for (int o = 16; o; o >>= 1) {
        float ov = __shfl_xor_sync(0xffffffffu, bv, o);
        int   oi = __shfl_xor_sync(0xffffffffu, bi, o);
        if (ov > bv || (ov == bv && oi < bi)) { bv = ov; bi = oi; }
    }
    if (lane == 0) {
        labels[row] = bi;
        const int ptr = load_ptr_val(ptr_in);
        const int ptrc = clamp_ptr(ptr);
        float lab = (float)bi;
        cont_labels[row] = lab;
        cont_labels[BB + row] = lab;
        new_qp[ptrc + row] = lab;
        if (row == 0) new_ptr_out[0] = (float)((ptr + BB) % QQ);
    }
}

// ---------------------------------------------------------------------------
// bulk role: queue dup + k scatter + q/k dup + qp dup.
// ---------------------------------------------------------------------------
#define NQ4     (QQ * DD / 4)      // 2,097,152
#define NB4     (BB * DD / 4)      // 131,072
#define BULK_SEG (NQ4 / 16)        // 131,072

__device__ void bulk_role(int bb,
    const float4* __restrict__ q4, const float4* __restrict__ k4,
    const float4* __restrict__ queue4, const float* __restrict__ qp,
    const void* __restrict__ ptr_in,
    float4* __restrict__ contf4, float4* __restrict__ outq4,
    float* __restrict__ outqp, float* __restrict__ contl)
{
    const int tid = threadIdx.x;
    const int ptrc = clamp_ptr(load_ptr_val(ptr_in));
    const int i = bb * 256 + tid;     // 0..131071 == NB4, exact

#pragma unroll
    for (int b = 0; b < 4; b++) {
        float4 v[4];
#pragma unroll
        for (int h = 0; h < 4; h++)
            v[h] = __ldcs(&queue4[i + (b * 4 + h) * BULK_SEG]);
#pragma unroll
        for (int h = 0; h < 4; h++)
            __stcs(&contf4[2 * NB4 + i + (b * 4 + h) * BULK_SEG], v[h]);
#pragma unroll
        for (int h = 0; h < 4; h++) {
            int idx = i + (b * 4 + h) * BULK_SEG;
            int row = idx >> 5;                        // 32 float4 per row
            float4 o = v[h];
            if (row >= ptrc && row < ptrc + BB)
                o = __ldcs(&k4[(row - ptrc) * 32 + (idx & 31)]);
            __stcs(&outq4[idx], o);                    // new_queue
        }
    }
    {
        float4 vq = __ldcs(&q4[i]);
        float4 vk = __ldcs(&k4[i]);
        __stcs(&contf4[i], vq);
        __stcs(&contf4[NB4 + i], vk);
    }
    if (i < QQ) {
        float v0 = __ldcs(&qp[i]);
        __stcs(&contl[2 * BB + i], v0);            // cont_labels tail
        if (i < ptrc || i >= ptrc + BB)
            __stcs(&outqp[i], v0);                 // new_queue_pseudo
    }
}

// ---------------------------------------------------------------------------
// Kernel 1: head — interleaved [gemm, classfy, bulk] x 512 groups.
// __launch_bounds__(256, 4): cap regs at 64 -> 4 blocks/SM.
// ---------------------------------------------------------------------------
#define HEAD_GRID (512 * 3)

__global__ __launch_bounds__(256, 4) void head_kernel(
    const float* __restrict__ q, const float* __restrict__ protos,
    float* __restrict__ escratch, float* __restrict__ psum,
    const float4* __restrict__ logits4, const float4* __restrict__ plabel4,
    const void* __restrict__ ptr_in,
    float4* __restrict__ out_classfy4, int* __restrict__ labels,
    float* __restrict__ cont_labels, float* __restrict__ new_qp,
    float* __restrict__ new_ptr_out,
    const float4* __restrict__ k4, const float4* __restrict__ queue4,
    const float* __restrict__ qp,
    float4* __restrict__ contf4, float4* __restrict__ outq4,
    float* __restrict__ outqp)
{
    extern __shared__ uint32_t smem[];
    const int grp = blockIdx.x / 3;
    const int r   = blockIdx.x % 3;
    if (r == 0) {
        gemm_role(grp, smem, q, protos, escratch, psum);
    } else if (r == 1) {
        classfy_role(grp, logits4, plabel4, ptr_in,
                     out_classfy4, labels, cont_labels, new_qp, new_ptr_out);
    } else {
        bulk_role(grp, (const float4*)q, k4, queue4, qp, ptr_in,
                  contf4, outq4, outqp, cont_labels);
    }
}

// ---------------------------------------------------------------------------
// Kernel 2: tail — interleaved [norm, proto, proto] x 512 groups.
// ---------------------------------------------------------------------------
#define TAIL_GRID (512 * 3)

__global__ __launch_bounds__(256) void tail_kernel(
    const float4* __restrict__ escratch4, const float* __restrict__ psum,
    const float* __restrict__ qf, const float* __restrict__ protos,
    const int* __restrict__ labels,
    float4* __restrict__ cluster4, float* __restrict__ out_proto)
{
    const int grp = blockIdx.x / 3;
    const int r   = blockIdx.x % 3;
    const int tid = threadIdx.x;

    if (r == 0) {
        // normalize role: warp-per-row, 8 rows
        const int w    = tid >> 5;
        const int lane = tid & 31;
        const int row  = grp * 8 + w;                  // 0..4095
        const int RF4  = CC / 4;                       // 250
        const float4* ps4 = (const float4*)(psum + (size_t)row * 8);
        float4 p0 = __ldg(&ps4[0]);
        float4 p1 = __ldg(&ps4[1]);
        const float inv = 1.0f /
            (p0.x + p0.y + p0.z + p0.w + p1.x + p1.y + p1.z + p1.w);
        const float4* src = escratch4 + (size_t)row * RF4;
        float4* dst = cluster4 + (size_t)row * RF4;
#pragma unroll
        for (int j = 0; j < 8; j++) {
            int c4 = j * 32 + lane;
            if (c4 < RF4) {
                float4 e = __ldcs(&src[c4]);
                e.x *= inv; e.y *= inv; e.z *= inv; e.w *= inv;
                __stcs(&dst[c4], e);
            }
        }
    } else {
        // prototype EMA role (warp-shuffle scan, 2 barriers)
        const int c = grp * 2 + (r - 1);               // 0..1023
        if (c >= CC) return;
        const int w    = tid >> 5;
        const int lane = tid & 31;
        __shared__ int idxbuf[BB];
        __shared__ int wsum[8];
        __shared__ float ws[4];

        const int4* lab4 = (const int4*)labels;
        int4 lv[4];
#pragma unroll
        for (int j = 0; j < 4; j++) lv[j] = __ldg(&lab4[tid * 4 + j]);
        int cnt = 0;
#pragma unroll
        for (int j = 0; j < 4; j++)
            cnt += (lv[j].x == c) + (lv[j].y == c) + (lv[j].z == c) + (lv[j].w == c);

        int inc = cnt;
#pragma unroll
        for (int d = 1; d < 32; d <<= 1) {
            int v = __shfl_up_sync(0xffffffffu, inc, d);
            if (lane >= d) inc += v;
        }
        if (lane == 31) wsum[w] = inc;
        __syncthreads();
        int wbase = 0, total = 0;
#pragma unroll
        for (int u = 0; u < 8; u++) {
            int s = wsum[u];
            if (u < w) wbase += s;
            total += s;
        }
        int wofs = wbase + inc - cnt;
        const int base = tid * 16;
#pragma unroll
        for (int j = 0; j < 4; j++) {
            if (lv[j].x == c) idxbuf[wofs++] = base + 4 * j;
            if (lv[j].y == c) idxbuf[wofs++] = base + 4 * j + 1;
            if (lv[j].z == c) idxbuf[wofs++] = base + 4 * j + 2;
            if (lv[j].w == c) idxbuf[wofs++] = base + 4 * j + 3;
        }
        __syncthreads();

        float acc = 0.f;
        if (tid < DD) {
            acc = protos[(size_t)c * DD + tid];
            for (int j = 0; j < total; j++)
                acc = PROTO_M * acc + (1.0f - PROTO_M) * qf[(size_t)idxbuf[j] * DD + tid];
        }
        float s = acc * acc;
#pragma unroll
        for (int o = 16; o; o >>= 1) s += __shfl_xor_sync(0xffffffffu, s, o);
        if (tid < DD && (tid & 31) == 0) ws[tid >> 5] = s;
        __syncthreads();
        if (tid < DD) {
            float tot = ws[0] + ws[1] + ws[2] + ws[3];
            float inv = 1.0f / fmaxf(sqrtf(tot), 1e-12f);
            out_proto[(size_t)c * DD + tid] = acc * inv;
        }
    }
}

// ---------------------------------------------------------------------------
static bool g_init = false;

extern "C" void kernel_launch(void* const* d_in, const int* in_sizes, int n_in,
                              void* d_out, int out_size)
{
    const float* q       = (const float*)d_in[0];
    const float* k       = (const float*)d_in[1];
    const float* logits  = (const float*)d_in[2];
    const float* plabel  = (const float*)d_in[3];
    const float* protos  = (const float*)d_in[4];
    const float* queue   = (const float*)d_in[5];
    const float* queuep  = (const float*)d_in[6];
    const void*  ptr_in  = d_in[7];

    float* out = (float*)d_out;
    float* out_classfy = out + OFF_CLASSFY;
    float* out_cluster = out + OFF_CLUSTER;
    float* out_contf   = out + OFF_CONTF;
    float* out_contl   = out + OFF_CONTL;
    float* out_proto   = out + OFF_PROTO;
    float* out_queue   = out + OFF_QUEUE;
    float* out_qp      = out + OFF_QP;
    float* out_ptr     = out + OFF_PTR;

    float* escratch;
    cudaGetSymbolAddress((void**)&escratch, g_logits);
    float* psum;
    cudaGetSymbolAddress((void**)&psum, g_psum);
    int* labels;
    cudaGetSymbolAddress((void**)&labels, g_labels);

    if (!g_init) {
        cudaFuncSetAttribute(head_kernel,
                             cudaFuncAttributeMaxDynamicSharedMemorySize,
                             GEMM_SMEM_BYTES);
        g_init = true;
    }

    cudaStream_t s = 0;

    // 1) head: gemm + classfy + bulk, interleaved roles
    head_kernel<<<HEAD_GRID, 256, GEMM_SMEM_BYTES, s>>>(
        q, protos, escratch, psum,
        (const float4*)logits, (const float4*)plabel, ptr_in,
        (float4*)out_classfy, labels, out_contl, out_qp, out_ptr,
        (const float4*)k, (const float4*)queue, queuep,
        (float4*)out_contf, (float4*)out_queue, out_qp);

    // 2) tail: normalize + proto EMA, interleaved roles
    tail_kernel<<<TAIL_GRID, 256, 0, s>>>(
        (const float4*)escratch, psum, q, protos, labels,
        (float4*)out_cluster, out_proto);
}

// round 12
// speedup vs baseline: 2.3508x; 1.0889x over previous
#include <cuda_runtime.h>
#include <cuda_bf16.h>
#include <math.h>
#include <stdint.h>

// Problem constants
#define BB 4096     // batch
#define CC 1000     // classes
#define DD 128      // feature dim
#define QQ 65536    // queue length
#define PROTO_M 0.99f

// ---- output layout (flat float32 concat, reference return order) ----
static const size_t OFF_CLASSFY = 0;
static const size_t OFF_CLUSTER = (size_t)BB * CC;
static const size_t OFF_CONTF   = OFF_CLUSTER + (size_t)BB * CC;
static const size_t OFF_CONTL   = OFF_CONTF + (size_t)(2 * BB + QQ) * DD;
static const size_t OFF_PROTO   = OFF_CONTL + (size_t)(2 * BB + QQ);
static const size_t OFF_QUEUE   = OFF_PROTO + (size_t)CC * DD;
static const size_t OFF_QP      = OFF_QUEUE + (size_t)QQ * DD;
static const size_t OFF_PTR     = OFF_QP + (size_t)QQ;

// scratch (no allocations allowed -> device globals)
__device__ float g_logits[(size_t)BB * CC];  // exp(logit) after head
__device__ float g_psum[(size_t)BB * 8];     // per-(row, n-block) exp partial sums
__device__ int   g_labels[BB];

// ---------------------------------------------------------------------------
__device__ __forceinline__ int load_ptr_val(const void* p)
{
    int iv = *(const int*)p;
    if (iv >= 0 && iv <= QQ) return iv;       // stored as int32
    float fv = *(const float*)p;              // stored as float32
    return (int)fv;
}
__device__ __forceinline__ int clamp_ptr(int ptr)
{
    int ptrc = ptr;
    if (ptrc < 0) ptrc = 0;
    if (ptrc > QQ - BB) ptrc = QQ - BB;
    return ptrc;
}

// ---------------------------------------------------------------------------
// tf32 helpers
// ---------------------------------------------------------------------------
__device__ __forceinline__ uint32_t f32_to_tf32(float f)
{
    uint32_t r;
    asm volatile("cvt.rna.tf32.f32 %0, %1;" : "=r"(r) : "f"(f));
    return r;
}

__device__ __forceinline__ void mma_tf32(float c[4],
    uint32_t a0, uint32_t a1, uint32_t a2, uint32_t a3,
    uint32_t b0, uint32_t b1)
{
    asm volatile(
        "mma.sync.aligned.m16n8k8.row.col.f32.tf32.tf32.f32 "
        "{%0,%1,%2,%3}, {%4,%5,%6,%7}, {%8,%9}, {%0,%1,%2,%3};"
        : "+f"(c[0]), "+f"(c[1]), "+f"(c[2]), "+f"(c[3])
        : "r"(a0), "r"(a1), "r"(a2), "r"(a3), "r"(b0), "r"(b1));
}

#define TBM 64
#define TBN 128
#define TBK 64
#define LDPK (TBK + 4)   // 68 words per smem row
#define GEMM_SMEM_BYTES ((TBM + TBN) * LDPK * 4)   // 52,224 bytes

// ---------------------------------------------------------------------------
// gemm role: exp(q @ protos^T) + per-(row, n-block) partial sums.
// ---------------------------------------------------------------------------
__device__ void gemm_role(int gb, uint32_t* smem,
    const float* __restrict__ Aq, const float* __restrict__ Bp,
    float* __restrict__ Eout, float* __restrict__ psum)
{
    uint32_t* As = smem;                  // [TBM][LDPK]
    uint32_t* Bs = smem + TBM * LDPK;     // [TBN][LDPK]
    __shared__ float smem_part[TBM][4];

    const int tid  = threadIdx.x;
    const int lane = tid & 31;
    const int w    = tid >> 5;
    const int wm   = w & 1;
    const int wn   = w >> 1;
    const int g    = lane >> 2;
    const int tig  = lane & 3;
    const int bx   = gb & 7;              // 8 n-blocks
    const int by   = gb >> 3;             // 64 m-blocks
    const int m0   = by * TBM;
    const int n0   = bx * TBN;
    const int rbase = wm * 32;
    const int cbase = wn * 32;

    float c[2][4][4];
#pragma unroll
    for (int mt = 0; mt < 2; mt++)
#pragma unroll
        for (int nt = 0; nt < 4; nt++)
#pragma unroll
            for (int i = 0; i < 4; i++) c[mt][nt][i] = 0.f;

#pragma unroll
    for (int kt = 0; kt < 2; kt++) {
        const int kk = kt * TBK;
        if (kt > 0) __syncthreads();
#pragma unroll
        for (int it = 0; it < 6; it++) {
            int slot = it * 256 + tid;
            float4 lo, hi;
            uint32_t* dst;
            if (slot < TBM * 8) {
                int r = slot >> 3, gp = slot & 7;
                const float* src = Aq + (size_t)(m0 + r) * DD + kk + gp * 8;
                lo = *(const float4*)src;
                hi = *(const float4*)(src + 4);
                dst = As + r * LDPK + gp * 8;
            } else {
                int s = slot - TBM * 8;
                int r = s >> 3, gp = s & 7;
                int n = n0 + r;
                if (n < CC) {
                    const float* src = Bp + (size_t)n * DD + kk + gp * 8;
                    lo = *(const float4*)src;
                    hi = *(const float4*)(src + 4);
                } else {
                    lo = make_float4(0.f, 0.f, 0.f, 0.f);
                    hi = lo;
                }
                dst = Bs + r * LDPK + gp * 8;
            }
            uint4 o0, o1;
            o0.x = f32_to_tf32(lo.x); o0.y = f32_to_tf32(hi.x);
            o0.z = f32_to_tf32(lo.y); o0.w = f32_to_tf32(hi.y);
            o1.x = f32_to_tf32(lo.z); o1.y = f32_to_tf32(hi.z);
            o1.z = f32_to_tf32(lo.w); o1.w = f32_to_tf32(hi.w);
            *(uint4*)dst = o0;
            *(uint4*)(dst + 4) = o1;
        }
        __syncthreads();

#pragma unroll
        for (int ks = 0; ks < TBK / 8; ks++) {
            const int k0 = ks * 8;
            uint2 afr[2][2];
#pragma unroll
            for (int mt = 0; mt < 2; mt++) {
                int rb = rbase + mt * 16 + g;
                afr[mt][0] = *(const uint2*)(As + rb * LDPK + k0 + 2 * tig);
                afr[mt][1] = *(const uint2*)(As + (rb + 8) * LDPK + k0 + 2 * tig);
            }
            uint2 bfr[4];
#pragma unroll
            for (int nt = 0; nt < 4; nt++) {
                int cb = cbase + nt * 8 + g;
                bfr[nt] = *(const uint2*)(Bs + cb * LDPK + k0 + 2 * tig);
            }
#pragma unroll
            for (int mt = 0; mt < 2; mt++)
#pragma unroll
                for (int nt = 0; nt < 4; nt++)
                    mma_tf32(c[mt][nt],
                             afr[mt][0].x, afr[mt][1].x, afr[mt][0].y, afr[mt][1].y,
                             bfr[nt].x, bfr[nt].y);
        }
    }

    // epilogue: exp, store, per-row partial sums (deterministic)
    float rs[2][2] = {{0.f, 0.f}, {0.f, 0.f}};
#pragma unroll
    for (int mt = 0; mt < 2; mt++) {
#pragma unroll
        for (int nt = 0; nt < 4; nt++) {
            int m = m0 + rbase + mt * 16 + g;
            int n = n0 + cbase + nt * 8 + 2 * tig;
            if (n < CC) {
                float e0 = __expf(c[mt][nt][0]);
                float e1 = __expf(c[mt][nt][1]);
                float e2 = __expf(c[mt][nt][2]);
                float e3 = __expf(c[mt][nt][3]);
                *(float2*)(Eout + (size_t)m * CC + n) = make_float2(e0, e1);
                *(float2*)(Eout + (size_t)(m + 8) * CC + n) = make_float2(e2, e3);
                rs[mt][0] += e0 + e1;
                rs[mt][1] += e2 + e3;
            }
        }
    }
#pragma unroll
    for (int o = 1; o <= 2; o <<= 1) {
#pragma unroll
        for (int mt = 0; mt < 2; mt++) {
            rs[mt][0] += __shfl_xor_sync(0xffffffffu, rs[mt][0], o);
            rs[mt][1] += __shfl_xor_sync(0xffffffffu, rs[mt][1], o);
        }
    }
    if (tig == 0) {
#pragma unroll
        for (int mt = 0; mt < 2; mt++) {
            smem_part[rbase + mt * 16 + g][wn]     = rs[mt][0];
            smem_part[rbase + mt * 16 + 8 + g][wn] = rs[mt][1];
        }
    }
    __syncthreads();
    if (tid < TBM) {
        float s = smem_part[tid][0] + smem_part[tid][1]
                + smem_part[tid][2] + smem_part[tid][3];
        psum[(size_t)(m0 + tid) * 8 + bx] = s;
    }
}

// ---------------------------------------------------------------------------
// classfy role: warp-per-row softmax + argmax(softmax*plabel) + labels epi.
// ---------------------------------------------------------------------------
__device__ void classfy_role(int cb,
    const float4* __restrict__ logits4, const float4* __restrict__ plabel4,
    const void* __restrict__ ptr_in,
    float4* __restrict__ out4, int* __restrict__ labels,
    float* __restrict__ cont_labels, float* __restrict__ new_qp,
    float* __restrict__ new_ptr_out)
{
    const int tid  = threadIdx.x;
    const int w    = tid >> 5;
    const int lane = tid & 31;
    const int row  = cb * 8 + w;
    const int RF4  = CC / 4;               // 250
    const float4* lrow = logits4 + (size_t)row * RF4;
    const float4* prow = plabel4 + (size_t)row * RF4;
    float4* orow = out4 + (size_t)row * RF4;

    float4 l[8];
    float mx = -1e30f;
#pragma unroll
    for (int j = 0; j < 8; j++) {
        int c4 = j * 32 + lane;
        if (c4 < RF4) {
            l[j] = lrow[c4];
            mx = fmaxf(mx, fmaxf(fmaxf(l[j].x, l[j].y), fmaxf(l[j].z, l[j].w)));
        } else {
            l[j] = make_float4(-1e30f, -1e30f, -1e30f, -1e30f);
        }
    }
#pragma unroll
    for (int o = 16; o; o >>= 1) mx = fmaxf(mx, __shfl_xor_sync(0xffffffffu, mx, o));

    float sum = 0.f;
#pragma unroll
    for (int j = 0; j < 8; j++) {
        l[j].x = __expf(l[j].x - mx);
        l[j].y = __expf(l[j].y - mx);
        l[j].z = __expf(l[j].z - mx);
        l[j].w = __expf(l[j].w - mx);
        sum += l[j].x + l[j].y + l[j].z + l[j].w;
    }
#pragma unroll
    for (int o = 16; o; o >>= 1) sum += __shfl_xor_sync(0xffffffffu, sum, o);
    const float inv = 1.0f / sum;

    float bv = -1.0f;
    int bi = 0x7fffffff;
#pragma unroll
    for (int j = 0; j < 8; j++) {
        int c4 = j * 32 + lane;
        if (c4 < RF4) {
            float4 p = prow[c4];
            float4 o;
            o.x = l[j].x * inv; o.y = l[j].y * inv;
            o.z = l[j].z * inv; o.w = l[j].w * inv;
            orow[c4] = o;
            float v0 = o.x * p.x, v1 = o.y * p.y, v2 = o.z * p.z, v3 = o.w * p.w;
            if (v0 > bv) { bv = v0; bi = 4 * c4; }
            if (v1 > bv) { bv = v1; bi = 4 * c4 + 1; }
            if (v2 > bv) { bv = v2; bi = 4 * c4 + 2; }
            if (v3 > bv) { bv = v3; bi = 4 * c4 + 3; }
        }
    }
#pragma unroll
    for (int o = 16; o; o >>= 1) {
        float ov = __shfl_xor_sync(0xffffffffu, bv, o);
        int   oi = __shfl_xor_sync(0xffffffffu, bi, o);
        if (ov > bv || (ov == bv && oi < bi)) { bv = ov; bi = oi; }
    }
    if (lane == 0) {
        labels[row] = bi;
        const int ptr = load_ptr_val(ptr_in);
        const int ptrc = clamp_ptr(ptr);
        float lab = (float)bi;
        cont_labels[row] = lab;
        cont_labels[BB + row] = lab;
        new_qp[ptrc + row] = lab;
        if (row == 0) new_ptr_out[0] = (float)((ptr + BB) % QQ);
    }
}

// ---------------------------------------------------------------------------
// bulk role: queue dup + k scatter + q/k dup + qp dup.
// ---------------------------------------------------------------------------
#define NQ4     (QQ * DD / 4)      // 2,097,152
#define NB4     (BB * DD / 4)      // 131,072
#define BULK_SEG (NQ4 / 16)        // 131,072

__device__ void bulk_role(int bb,
    const float4* __restrict__ q4, const float4* __restrict__ k4,
    const float4* __restrict__ queue4, const float* __restrict__ qp,
    const void* __restrict__ ptr_in,
    float4* __restrict__ contf4, float4* __restrict__ outq4,
    float* __restrict__ outqp, float* __restrict__ contl)
{
    const int tid = threadIdx.x;
    const int ptrc = clamp_ptr(load_ptr_val(ptr_in));
    const int i = bb * 256 + tid;     // 0..131071 == NB4, exact

#pragma unroll
    for (int b = 0; b < 4; b++) {
        float4 v[4];
#pragma unroll
        for (int h = 0; h < 4; h++)
            v[h] = __ldcs(&queue4[i + (b * 4 + h) * BULK_SEG]);
#pragma unroll
        for (int h = 0; h < 4; h++)
            __stcs(&contf4[2 * NB4 + i + (b * 4 + h) * BULK_SEG], v[h]);
#pragma unroll
        for (int h = 0; h < 4; h++) {
            int idx = i + (b * 4 + h) * BULK_SEG;
            int row = idx >> 5;                        // 32 float4 per row
            float4 o = v[h];
            if (row >= ptrc && row < ptrc + BB)
                o = __ldcs(&k4[(row - ptrc) * 32 + (idx & 31)]);
            __stcs(&outq4[idx], o);                    // new_queue
        }
    }
    {
        float4 vq = __ldcs(&q4[i]);
        float4 vk = __ldcs(&k4[i]);
        __stcs(&contf4[i], vq);
        __stcs(&contf4[NB4 + i], vk);
    }
    if (i < QQ) {
        float v0 = __ldcs(&qp[i]);
        __stcs(&contl[2 * BB + i], v0);            // cont_labels tail
        if (i < ptrc || i >= ptrc + BB)
            __stcs(&outqp[i], v0);                 // new_queue_pseudo
    }
}

// ---------------------------------------------------------------------------
// Kernel 1: head — interleaved [gemm, classfy, bulk] x 512 groups (R8 exact).
// ---------------------------------------------------------------------------
#define HEAD_GRID (512 * 3)

__global__ __launch_bounds__(256) void head_kernel(
    const float* __restrict__ q, const float* __restrict__ protos,
    float* __restrict__ escratch, float* __restrict__ psum,
    const float4* __restrict__ logits4, const float4* __restrict__ plabel4,
    const void* __restrict__ ptr_in,
    float4* __restrict__ out_classfy4, int* __restrict__ labels,
    float* __restrict__ cont_labels, float* __restrict__ new_qp,
    float* __restrict__ new_ptr_out,
    const float4* __restrict__ k4, const float4* __restrict__ queue4,
    const float* __restrict__ qp,
    float4* __restrict__ contf4, float4* __restrict__ outq4,
    float* __restrict__ outqp)
{
    extern __shared__ uint32_t smem[];
    const int grp = blockIdx.x / 3;
    const int r   = blockIdx.x % 3;
    if (r == 0) {
        gemm_role(grp, smem, q, protos, escratch, psum);
    } else if (r == 1) {
        classfy_role(grp, logits4, plabel4, ptr_in,
                     out_classfy4, labels, cont_labels, new_qp, new_ptr_out);
    } else {
        bulk_role(grp, (const float4*)q, k4, queue4, qp, ptr_in,
                  contf4, outq4, outqp, cont_labels);
    }
}

// ---------------------------------------------------------------------------
// Kernel 2: tail — interleaved [norm, proto, proto] x 512 groups.
// proto EMA uses the weighted-sum form: independent q loads (MLP), no
// dependent global-load chain.
// ---------------------------------------------------------------------------
#define TAIL_GRID (512 * 3)

__global__ __launch_bounds__(256) void tail_kernel(
    const float4* __restrict__ escratch4, const float* __restrict__ psum,
    const float* __restrict__ qf, const float* __restrict__ protos,
    const int* __restrict__ labels,
    float4* __restrict__ cluster4, float* __restrict__ out_proto)
{
    const int grp = blockIdx.x / 3;
    const int r   = blockIdx.x % 3;
    const int tid = threadIdx.x;

    if (r == 0) {
        // normalize role: warp-per-row, 8 rows (R8 exact)
        const int w    = tid >> 5;
        const int lane = tid & 31;
        const int row  = grp * 8 + w;                  // 0..4095
        const int RF4  = CC / 4;                       // 250
        float total = 0.f;
#pragma unroll
        for (int j = 0; j < 8; j++) total += psum[(size_t)row * 8 + j];
        const float inv = 1.0f / total;
        const float4* src = escratch4 + (size_t)row * RF4;
        float4* dst = cluster4 + (size_t)row * RF4;
#pragma unroll
        for (int j = 0; j < 8; j++) {
            int c4 = j * 32 + lane;
            if (c4 < RF4) {
                float4 e = src[c4];
                e.x *= inv; e.y *= inv; e.z *= inv; e.w *= inv;
                dst[c4] = e;
            }
        }
    } else {
        // prototype EMA role: warp-shuffle scan + weighted-sum EMA
        const int c = grp * 2 + (r - 1);               // 0..1023
        if (c >= CC) return;
        const int w    = tid >> 5;
        const int lane = tid & 31;
        __shared__ int idxbuf[BB];
        __shared__ int wsum[8];
        __shared__ float ws[4];

        const int4* lab4 = (const int4*)labels;
        int4 lv[4];
#pragma unroll
        for (int j = 0; j < 4; j++) lv[j] = __ldg(&lab4[tid * 4 + j]);
        int cnt = 0;
#pragma unroll
        for (int j = 0; j < 4; j++)
            cnt += (lv[j].x == c) + (lv[j].y == c) + (lv[j].z == c) + (lv[j].w == c);

        int inc = cnt;
#pragma unroll
        for (int d = 1; d < 32; d <<= 1) {
            int v = __shfl_up_sync(0xffffffffu, inc, d);
            if (lane >= d) inc += v;
        }
        if (lane == 31) wsum[w] = inc;
        __syncthreads();
        int wbase = 0, total = 0;
#pragma unroll
        for (int u = 0; u < 8; u++) {
            int s = wsum[u];
            if (u < w) wbase += s;
            total += s;
        }
        int wofs = wbase + inc - cnt;
        const int base = tid * 16;
#pragma unroll
        for (int j = 0; j < 4; j++) {
            if (lv[j].x == c) idxbuf[wofs++] = base + 4 * j;
            if (lv[j].y == c) idxbuf[wofs++] = base + 4 * j + 1;
            if (lv[j].z == c) idxbuf[wofs++] = base + 4 * j + 2;
            if (lv[j].w == c) idxbuf[wofs++] = base + 4 * j + 3;
        }
        __syncthreads();

        float acc = 0.f;
        if (tid < DD) {
            // weighted-sum EMA: acc = m^T * proto + sum_j (1-m) m^{T-1-j} q_j
            // iterate j descending so the weight recurrence is a cheap FMA
            // chain while the q loads stay independent (full MLP).
            acc = __powf(PROTO_M, (float)total) * protos[(size_t)c * DD + tid];
            float wgt = 1.0f - PROTO_M;    // weight for j = total-1
#pragma unroll 4
            for (int j = total - 1; j >= 0; j--) {
                acc += wgt * qf[(size_t)idxbuf[j] * DD + tid];
                wgt *= PROTO_M;
            }
        }
        float s = acc * acc;
#pragma unroll
        for (int o = 16; o; o >>= 1) s += __shfl_xor_sync(0xffffffffu, s, o);
        if (tid < DD && (tid & 31) == 0) ws[tid >> 5] = s;
        __syncthreads();
        if (tid < DD) {
            float tot = ws[0] + ws[1] + ws[2] + ws[3];
            float inv = 1.0f / fmaxf(sqrtf(tot), 1e-12f);
            out_proto[(size_t)c * DD + tid] = acc * inv;
        }
    }
}

// ---------------------------------------------------------------------------
static bool g_init = false;

extern "C" void kernel_launch(void* const* d_in, const int* in_sizes, int n_in,
                              void* d_out, int out_size)
{
    const float* q       = (const float*)d_in[0];
    const float* k       = (const float*)d_in[1];
    const float* logits  = (const float*)d_in[2];
    const float* plabel  = (const float*)d_in[3];
    const float* protos  = (const float*)d_in[4];
    const float* queue   = (const float*)d_in[5];
    const float* queuep  = (const float*)d_in[6];
    const void*  ptr_in  = d_in[7];

    float* out = (float*)d_out;
    float* out_classfy = out + OFF_CLASSFY;
    float* out_cluster = out + OFF_CLUSTER;
    float* out_contf   = out + OFF_CONTF;
    float* out_contl   = out + OFF_CONTL;
    float* out_proto   = out + OFF_PROTO;
    float* out_queue   = out + OFF_QUEUE;
    float* out_qp      = out + OFF_QP;
    float* out_ptr     = out + OFF_PTR;

    float* escratch;
    cudaGetSymbolAddress((void**)&escratch, g_logits);
    float* psum;
    cudaGetSymbolAddress((void**)&psum, g_psum);
    int* labels;
    cudaGetSymbolAddress((void**)&labels, g_labels);

    if (!g_init) {
        cudaFuncSetAttribute(head_kernel,
                             cudaFuncAttributeMaxDynamicSharedMemorySize,
                             GEMM_SMEM_BYTES);
        g_init = true;
    }

    cudaStream_t s = 0;

    // 1) head: gemm + classfy + bulk, interleaved roles (R8 exact)
    head_kernel<<<HEAD_GRID, 256, GEMM_SMEM_BYTES, s>>>(
        q, protos, escratch, psum,
        (const float4*)logits, (const float4*)plabel, ptr_in,
        (float4*)out_classfy, labels, out_contl, out_qp, out_ptr,
        (const float4*)k, (const float4*)queue, queuep,
        (float4*)out_contf, (float4*)out_queue, out_qp);

    // 2) tail: normalize + proto EMA (weighted-sum), interleaved roles
    tail_kernel<<<TAIL_GRID, 256, 0, s>>>(
        (const float4*)escratch, psum, q, protos, labels,
        (float4*)out_cluster, out_proto);
}